// round 13
// baseline (speedup 1.0000x reference)
#include <cuda_runtime.h>
#include <cuda_bf16.h>
#include <math.h>

#define NB 128
#define NL 100
#define NH 256
#define NIN 160
#define NG 1024
#define NCAP 1600
#define NCL 19
#define NOD 304
#define NCH 8
#define GSZ 8      // CTAs per LSTM group (hidden split)
#define GB  16     // batch rows per group
#define LSTM_SMEM (131072 + 16*260*4)

typedef unsigned long long ull;

// packed fp32x2 fma: c = a*b + c
#define FMA2(c,a,b) asm("fma.rn.f32x2 %0, %1, %2, %3;" : "=l"(c) : "l"(a), "l"(b), "l"(c))

__device__ __forceinline__ float unpack_sum(ull v){
    float lo, hi;
    asm("mov.b64 {%0,%1}, %2;" : "=f"(lo), "=f"(hi) : "l"(v));
    return lo + hi;
}

// pack two floats to bf16x2 (lo=x, hi=y)
__device__ __forceinline__ unsigned pack_bf16x2(float x, float y){
    unsigned r;
    asm("cvt.rn.bf16x2.f32 %0, %1, %2;" : "=r"(r) : "f"(y), "f"(x));
    return r;
}

// fast activations (MUFU-based)
__device__ __forceinline__ float ex2f(float x){
    float r; asm("ex2.approx.ftz.f32 %0, %1;" : "=f"(r) : "f"(x)); return r;
}
__device__ __forceinline__ float sigm_f(float x){
    return __fdividef(1.f, 1.f + ex2f(-1.4426950408889634f*x));
}
__device__ __forceinline__ float tanh_f(float x){
    float r; asm("tanh.approx.f32 %0, %1;" : "=f"(r) : "f"(x)); return r;
}

// ---------------- static device scratch (no allocations) ----------------
__device__ float g_emb[NL*NB*NIN];
__device__ float g_xg[2*NL*NG*NB];          // [dir][t][g][b]
__device__ float g_hx[2*8*2*GB*256];        // [dir][grp][parity][b16][u256]
__device__ float g_hall[2*NL*NB*NH];        // [dir][t][b][256]
__device__ float g_x[NB*NL*NH];
__device__ float g_u[NB*NCAP*16];
__device__ float g_att[NB*NL];
__device__ float g_cbase[NCAP*NCL];
__device__ __nv_bfloat16 g_uhat[(size_t)NB*NCAP*NOD];   // bf16: halves routing traffic
__device__ float g_bb[(size_t)NB*NCAP*NCL];
__device__ float g_spart[NB*NCH*NOD];
__device__ float g_v[NB*NOD];
__device__ unsigned g_gcnt[16*64];          // per-group barrier counters, 256B apart

// 0) zero the group counters (separate launch -> race-free base for k_lstm)
__global__ void k_zero(){
    if(threadIdx.x<16) g_gcnt[threadIdx.x*64]=0u;
}

// 1) embedding gather
__global__ void k_embed(const int* __restrict__ word,const int* __restrict__ tag,
                        const int* __restrict__ p1,const int* __restrict__ p2,
                        const float* __restrict__ we,const float* __restrict__ te,
                        const float* __restrict__ p1e,const float* __restrict__ p2e){
    int bl=blockIdx.x, t=bl/NB, b=bl%NB, d=threadIdx.x;
    float v;
    if(d<100)      v=we[(size_t)word[b*NL+t]*100+d];
    else if(d<120) v=te[tag[b*NL+t]*20+(d-100)];
    else if(d<140) v=p1e[p1[b*NL+t]*20+(d-120)];
    else           v=p2e[p2[b*NL+t]*20+(d-140)];
    g_emb[(t*NB+b)*NIN+d]=v;
}

// 2) xg = emb @ w_ih^T + b_ih + b_hh  -> [dir][t][g][b]
//    f32x2 packed along k; Es stride 22 floats -> 16 lanes hit 16 distinct banks.
__global__ __launch_bounds__(256) void k_xg(
        const float* __restrict__ wih_f,const float* __restrict__ wih_b,
        const float* __restrict__ bih_f,const float* __restrict__ bhh_f,
        const float* __restrict__ bih_b,const float* __restrict__ bhh_b){
    __shared__ __align__(16) float Ws[64*18];
    __shared__ __align__(16) float Es[64*22];
    int t=blockIdx.y, dir=blockIdx.z;
    int g0=(blockIdx.x&15)*64, b0=(blockIdx.x>>4)*64;
    const float* wih=dir?wih_b:wih_f;
    const float* bih=dir?bih_b:bih_f;
    const float* bhh=dir?bhh_b:bhh_f;
    int tid=threadIdx.x, tx=tid&15, ty=tid>>4;
    ull acc2[4][4];
    #pragma unroll
    for(int i=0;i<4;i++)
        #pragma unroll
        for(int j=0;j<4;j++) acc2[i][j]=0ull;
    for(int kk=0;kk<NIN;kk+=16){
        #pragma unroll
        for(int e=tid;e<1024;e+=256){
            int r=e>>4,c=e&15;
            Ws[r*18+c]=wih[(g0+r)*NIN+kk+c];
            Es[r*22+c]=g_emb[(t*NB+b0+r)*NIN+kk+c];
        }
        __syncthreads();
        #pragma unroll
        for(int k=0;k<16;k+=2){
            ull a2[4],e2[4];
            #pragma unroll
            for(int i=0;i<4;i++) a2[i]=*(const ull*)(Ws+(ty*4+i)*18+k);   // broadcast
            #pragma unroll
            for(int j=0;j<4;j++) e2[j]=*(const ull*)(Es+(tx*4+j)*22+k);   // conflict-free
            #pragma unroll
            for(int i=0;i<4;i++)
                #pragma unroll
                for(int j=0;j<4;j++) FMA2(acc2[i][j],a2[i],e2[j]);
        }
        __syncthreads();
    }
    #pragma unroll
    for(int i=0;i<4;i++){
        int g=g0+ty*4+i;
        float bias=bih[g]+bhh[g];
        float4 r4=make_float4(unpack_sum(acc2[i][0])+bias,unpack_sum(acc2[i][1])+bias,
                              unpack_sum(acc2[i][2])+bias,unpack_sum(acc2[i][3])+bias);
        *(float4*)(g_xg+((size_t)(dir*NL+t)*NG+g)*NB+b0+tx*4)=r4;
    }
}

// 3) persistent BiLSTM, group-local sync (R9 structure: best measured).
__global__ __launch_bounds__(256,1) void k_lstm(const float* __restrict__ whh_f,
                                                const float* __restrict__ whh_b){
    extern __shared__ float sm[];
    float* sW=sm;               // [lrow 0..127][k 0..255], lrow=gate*32+ul
    float* sH=sm+32768;         // [b 0..15][260]
    int tid=threadIdx.x, bid=blockIdx.x;
    int dir=bid>>6, grp=(bid>>3)&7, c=bid&7;
    int gid=dir*8+grp;
    const float* whh=dir?whh_b:whh_f;
    for(int e4=tid;e4<8192;e4+=256){
        int lrow=e4>>6, k4=(e4&63)*4;
        *(float4*)(sW+lrow*256+k4)=
            *(const float4*)(whh+(size_t)((lrow>>5)*256 + c*32 + (lrow&31))*256 + k4);
    }
    __syncthreads();
    int b=tid&15, usub=tid>>4;
    int bg=grp*GB+b;
    int u0=c*32+usub*2;
    float cst[2]={0.f,0.f};
    float* hxbase=g_hx+(size_t)gid*2*GB*256;    // [parity][b][u]
    unsigned* cnt=&g_gcnt[gid*64];
    const float* wbase=sW+usub*512;
    float xr[8];
    {
        int t0=dir?(NL-1):0;
        const float* xgp=g_xg+((size_t)(dir*NL+t0)*NG)*NB;
        #pragma unroll
        for(int r=0;r<8;r++){
            int g=(r>>1)*256 + u0 + (r&1);
            xr[r]=__ldcg(xgp+(size_t)g*NB+bg);
        }
    }
    for(int s=0;s<NL;s++){
        int t=dir?(NL-1-s):s;
        ull acc2[8]={0,0,0,0,0,0,0,0};
        if(s>0){
            const float* src=hxbase+(size_t)(s&1)*GB*256;
            for(int i4=tid;i4<1024;i4+=256){
                int bb=i4>>6, k4=(i4&63)*4;
                float4 v=__ldcg((const float4*)(src+bb*256+k4));
                *(float4*)(sH+bb*260+k4)=v;
            }
            __syncthreads();
            const float* hrow=sH+b*260;
            #pragma unroll 4
            for(int k=0;k<256;k+=4){
                ulonglong2 h2=*(const ulonglong2*)(hrow+k);
                #pragma unroll
                for(int r=0;r<8;r++){
                    const ulonglong2* w2=(const ulonglong2*)(wbase+(r>>1)*8192+(r&1)*256+k);
                    FMA2(acc2[r],h2.x,w2->x);
                    FMA2(acc2[r],h2.y,w2->y);
                }
            }
        }
        float acc[8];
        #pragma unroll
        for(int r=0;r<8;r++) acc[r]=unpack_sum(acc2[r])+xr[r];
        float* hw=hxbase+(size_t)((s+1)&1)*GB*256;
        float* hall=g_hall+((size_t)(dir*NL+t)*NB+bg)*NH;
        float hn[2];
        #pragma unroll
        for(int j=0;j<2;j++){
            float cn=sigm_f(acc[2+j])*cst[j]+sigm_f(acc[j])*tanh_f(acc[4+j]);
            cst[j]=cn;
            hn[j]=sigm_f(acc[6+j])*tanh_f(cn);
        }
        *(float2*)(hw+b*256+u0)=make_float2(hn[0],hn[1]);
        *(float2*)(hall+u0)=make_float2(hn[0],hn[1]);
        if(s<NL-1){
            int tn=dir?(NL-2-s):(s+1);
            const float* xgp=g_xg+((size_t)(dir*NL+tn)*NG)*NB;
            #pragma unroll
            for(int r=0;r<8;r++){
                int g=(r>>1)*256 + u0 + (r&1);
                xr[r]=__ldcg(xgp+(size_t)g*NB+bg);
            }
        }
        __threadfence();
        __syncthreads();
        if(tid==0){
            atomicAdd(cnt,1u);
            if(s<NL-1){
                unsigned tgt=(unsigned)(GSZ*(s+1));
                while(*((volatile unsigned*)cnt)<tgt) __nanosleep(32);
            }
        }
        __syncthreads();
        __threadfence();
    }
}

// 4) x = hf + hb ; u = squash(primary caps)
__global__ __launch_bounds__(256) void k_combine(){
    int bl=blockIdx.x, b=bl/NL, l=bl%NL, j=threadIdx.x;
    float v=g_hall[((size_t)(0*NL+l)*NB+b)*NH+j]+g_hall[((size_t)(1*NL+l)*NB+b)*NH+j];
    g_x[((size_t)b*NL+l)*NH+j]=v;
    float n2=v*v;
    n2+=__shfl_xor_sync(0xffffffffu,n2,1);
    n2+=__shfl_xor_sync(0xffffffffu,n2,2);
    n2+=__shfl_xor_sync(0xffffffffu,n2,4);
    n2+=__shfl_xor_sync(0xffffffffu,n2,8);
    float f=(n2/(1.f+n2))*rsqrtf(n2+1e-9f);
    g_u[((size_t)b*NCAP+l*16)*16+j]=v*f;
}

// 5) entity gather + attention softmax over L
__global__ __launch_bounds__(256) void k_att(const int* __restrict__ pos1,
                                             const int* __restrict__ pos2){
    __shared__ int se1,se2;
    __shared__ float she[NH];
    __shared__ float sd[NL];
    int b=blockIdx.x, tid=threadIdx.x;
    if(tid<NL){
        if(pos1[b*NL+tid]==68) se1=tid;
        if(pos2[b*NL+tid]==68) se2=tid;
    }
    __syncthreads();
    she[tid]=g_x[((size_t)b*NL+se1)*NH+tid]+g_x[((size_t)b*NL+se2)*NH+tid];
    __syncthreads();
    int warp=tid>>5, lane=tid&31;
    for(int l=warp;l<NL;l+=8){
        const float* xr=g_x+((size_t)b*NL+l)*NH;
        float s=0.f;
        for(int k=lane;k<NH;k+=32) s+=xr[k]*she[k];
        for(int m=16;m;m>>=1) s+=__shfl_xor_sync(0xffffffffu,s,m);
        if(lane==0) sd[l]=s;
    }
    __syncthreads();
    if(tid<32){
        float vals[4],mx=-1e30f;
        #pragma unroll
        for(int q=0;q<4;q++){
            int l=tid+32*q;
            vals[q]=(l<NL)?sd[l]:-1e30f;
            mx=fmaxf(mx,vals[q]);
        }
        for(int m=16;m;m>>=1) mx=fmaxf(mx,__shfl_xor_sync(0xffffffffu,mx,m));
        float es[4],ss=0.f;
        #pragma unroll
        for(int q=0;q<4;q++){
            int l=tid+32*q;
            es[q]=(l<NL)?expf(vals[q]-mx):0.f;
            ss+=es[q];
        }
        for(int m=16;m;m>>=1) ss+=__shfl_xor_sync(0xffffffffu,ss,m);
        float inv=1.f/ss;
        #pragma unroll
        for(int q=0;q<4;q++){
            int l=tid+32*q;
            if(l<NL) g_att[b*NL+l]=es[q]*inv;
        }
    }
}

// 6) softmax(b_route) once
__global__ void k_cbase(const float* __restrict__ br){
    int i=blockIdx.x, lane=threadIdx.x;
    float v=(lane<NCL)?br[i*NCL+lane]:-1e30f;
    float mx=v;
    for(int m=16;m;m>>=1) mx=fmaxf(mx,__shfl_xor_sync(0xffffffffu,mx,m));
    float e=(lane<NCL)?expf(v-mx):0.f;
    float s=e;
    for(int m=16;m;m>>=1) s+=__shfl_xor_sync(0xffffffffu,s,m);
    if(lane<NCL) g_cbase[i*NCL+lane]=e/s;
}

// 7) u_hat[b][i][:] = u[b][i][:16] @ W_caps[i]  -> bf16 output
__global__ __launch_bounds__(256) void k_uhat(const float* __restrict__ Wc){
    __shared__ float Ws[16*NOD];
    __shared__ float Ut[16*132];
    int i=blockIdx.x, tid=threadIdx.x;
    const float* wp=Wc+(size_t)i*16*NOD;
    for(int e=tid;e<16*NOD;e+=256) Ws[e]=wp[e];
    for(int e=tid;e<2048;e+=256){
        int bb_=e>>4,cc=e&15;
        Ut[cc*132+bb_]=g_u[((size_t)bb_*NCAP+i)*16+cc];
    }
    __syncthreads();
    for(int tI=tid;tI<32*76;tI+=256){
        int ot=tI%76, bt=tI/76, o0=ot*4, b0=bt*4;
        float acc[4][4];
        #pragma unroll
        for(int x=0;x<4;x++)
            #pragma unroll
            for(int y=0;y<4;y++) acc[x][y]=0.f;
        #pragma unroll
        for(int cc=0;cc<16;cc++){
            float4 u4=*(const float4*)(Ut+cc*132+b0);
            float4 w4=*(const float4*)(Ws+cc*NOD+o0);
            acc[0][0]+=u4.x*w4.x; acc[0][1]+=u4.x*w4.y; acc[0][2]+=u4.x*w4.z; acc[0][3]+=u4.x*w4.w;
            acc[1][0]+=u4.y*w4.x; acc[1][1]+=u4.y*w4.y; acc[1][2]+=u4.y*w4.z; acc[1][3]+=u4.y*w4.w;
            acc[2][0]+=u4.z*w4.x; acc[2][1]+=u4.z*w4.y; acc[2][2]+=u4.z*w4.z; acc[2][3]+=u4.z*w4.w;
            acc[3][0]+=u4.w*w4.x; acc[3][1]+=u4.w*w4.y; acc[3][2]+=u4.w*w4.z; acc[3][3]+=u4.w*w4.w;
        }
        #pragma unroll
        for(int bi=0;bi<4;bi++){
            uint2 p;
            p.x=pack_bf16x2(acc[bi][0],acc[bi][1]);
            p.y=pack_bf16x2(acc[bi][2],acc[bi][3]);
            *(uint2*)(g_uhat+((size_t)(b0+bi)*NCAP+i)*NOD+o0)=p;
        }
    }
}

// 8) fused routing pass (bf16 u_hat reads)
__global__ __launch_bounds__(320) void k_route(int mode,const float* __restrict__ b_route){
    __shared__ float sv[320];
    __shared__ float sag[32];
    __shared__ float sc[32];
    int tid=threadIdx.x, b=blockIdx.y, chunk=blockIdx.x;
    int o=tid>>4, d=tid&15;
    sv[tid]=(mode>0&&tid<NOD)?g_v[b*NOD+tid]:0.f;
    __syncthreads();
    int i0=chunk*(NCAP/NCH);
    float accS=0.f;
    float u=(tid<NOD)?__bfloat162float(g_uhat[((size_t)b*NCAP+i0)*NOD+tid]):0.f;
    for(int ii=0;ii<NCAP/NCH;ii++){
        int i=i0+ii;
        float unext=0.f;
        if(ii+1<NCAP/NCH&&tid<NOD)
            unext=__bfloat162float(g_uhat[((size_t)b*NCAP+i+1)*NOD+tid]);
        float atti=g_att[b*NL+(i>>4)];
        float cO;
        if(mode==0){
            cO=(o<NCL)?g_cbase[i*NCL+o]*atti:0.f;
        } else {
            float p=u*sv[tid];
            p+=__shfl_xor_sync(0xffffffffu,p,1);
            p+=__shfl_xor_sync(0xffffffffu,p,2);
            p+=__shfl_xor_sync(0xffffffffu,p,4);
            p+=__shfl_xor_sync(0xffffffffu,p,8);
            if(d==0&&o<NCL){
                float prior=(mode==1)?b_route[i*NCL+o]:g_bb[((size_t)b*NCAP+i)*NCL+o];
                float nb=prior+p;
                if(mode==1) g_bb[((size_t)b*NCAP+i)*NCL+o]=nb;
                sag[o]=nb;
            }
            __syncthreads();
            if(tid<32){
                float v=(tid<NCL)?sag[tid]:-1e30f;
                float mx=v;
                for(int m=16;m;m>>=1) mx=fmaxf(mx,__shfl_xor_sync(0xffffffffu,mx,m));
                float e=(tid<NCL)?expf(v-mx):0.f;
                float ss=e;
                for(int m=16;m;m>>=1) ss+=__shfl_xor_sync(0xffffffffu,ss,m);
                if(tid<NCL) sc[tid]=e/ss*atti;
            }
            __syncthreads();
            cO=(o<NCL)?sc[o]:0.f;
        }
        accS+=cO*u;
        u=unext;
    }
    if(tid<NOD) g_spart[(b*NCH+chunk)*NOD+tid]=accS;
}

// 9) reduce partials + squash -> v (or final class lengths)
__global__ __launch_bounds__(320) void k_reduce(int final_out,float* __restrict__ out){
    int b=blockIdx.x, tid=threadIdx.x;
    float s=0.f;
    if(tid<NOD){
        #pragma unroll
        for(int ch=0;ch<NCH;ch++) s+=g_spart[(b*NCH+ch)*NOD+tid];
    }
    float n2=s*s;
    n2+=__shfl_xor_sync(0xffffffffu,n2,1);
    n2+=__shfl_xor_sync(0xffffffffu,n2,2);
    n2+=__shfl_xor_sync(0xffffffffu,n2,4);
    n2+=__shfl_xor_sync(0xffffffffu,n2,8);
    float f=(n2/(1.f+n2))*rsqrtf(n2+1e-9f);
    if(!final_out){
        if(tid<NOD) g_v[b*NOD+tid]=s*f;
    } else {
        if(tid<NOD&&(tid&15)==0)
            out[b*NCL+(tid>>4)]=sqrtf(n2*f*f+1e-9f);
    }
}

extern "C" void kernel_launch(void* const* d_in,const int* in_sizes,int n_in,
                              void* d_out,int out_size){
    (void)in_sizes;(void)n_in;(void)out_size;
    const int*   word =(const int*)d_in[0];
    const int*   tag  =(const int*)d_in[1];
    const int*   pos1 =(const int*)d_in[2];
    const int*   pos2 =(const int*)d_in[3];
    const float* we   =(const float*)d_in[4];
    const float* te   =(const float*)d_in[5];
    const float* p1e  =(const float*)d_in[6];
    const float* p2e  =(const float*)d_in[7];
    const float* wih_f=(const float*)d_in[8];
    const float* whh_f=(const float*)d_in[9];
    const float* bih_f=(const float*)d_in[10];
    const float* bhh_f=(const float*)d_in[11];
    const float* wih_b=(const float*)d_in[12];
    const float* whh_b=(const float*)d_in[13];
    const float* bih_b=(const float*)d_in[14];
    const float* bhh_b=(const float*)d_in[15];
    const float* Wc   =(const float*)d_in[16];
    const float* br   =(const float*)d_in[17];
    float* out=(float*)d_out;

    cudaFuncSetAttribute(k_lstm, cudaFuncAttributeMaxDynamicSharedMemorySize, LSTM_SMEM);

    k_embed<<<NL*NB,160>>>(word,tag,pos1,pos2,we,te,p1e,p2e);
    k_cbase<<<NCAP,32>>>(br);
    k_xg<<<dim3(32,NL,2),256>>>(wih_f,wih_b,bih_f,bhh_f,bih_b,bhh_b);
    k_zero<<<1,32>>>();
    k_lstm<<<128,256,LSTM_SMEM>>>(whh_f,whh_b);
    k_combine<<<NB*NL,256>>>();
    k_att<<<NB,256>>>(pos1,pos2);
    k_uhat<<<NCAP,256>>>(Wc);
    k_route<<<dim3(NCH,NB),320>>>(0,br);
    k_reduce<<<NB,320>>>(0,out);
    k_route<<<dim3(NCH,NB),320>>>(1,br);
    k_reduce<<<NB,320>>>(0,out);
    k_route<<<dim3(NCH,NB),320>>>(2,br);
    k_reduce<<<NB,320>>>(1,out);
}

// round 14
// speedup vs baseline: 1.0482x; 1.0482x over previous
#include <cuda_runtime.h>
#include <cuda_bf16.h>
#include <math.h>

#define NB 128
#define NL 100
#define NH 256
#define NIN 160
#define NG 1024
#define NCAP 1600
#define NCL 19
#define NOD 304
#define NCH 8
#define GSZ 8      // CTAs per LSTM group (hidden split)
#define GB  16     // batch rows per group
#define LSTM_SMEM (131072 + 16*260*4)

typedef unsigned long long ull;

// packed fp32x2 fma: c = a*b + c
#define FMA2(c,a,b) asm("fma.rn.f32x2 %0, %1, %2, %3;" : "=l"(c) : "l"(a), "l"(b), "l"(c))

__device__ __forceinline__ float unpack_sum(ull v){
    float lo, hi;
    asm("mov.b64 {%0,%1}, %2;" : "=f"(lo), "=f"(hi) : "l"(v));
    return lo + hi;
}

// pack two floats to bf16x2 (lo=x, hi=y)
__device__ __forceinline__ unsigned pack_bf16x2(float x, float y){
    unsigned r;
    asm("cvt.rn.bf16x2.f32 %0, %1, %2;" : "=r"(r) : "f"(y), "f"(x));
    return r;
}

// fast activations (MUFU-based)
__device__ __forceinline__ float ex2f(float x){
    float r; asm("ex2.approx.ftz.f32 %0, %1;" : "=f"(r) : "f"(x)); return r;
}
__device__ __forceinline__ float sigm_f(float x){
    return __fdividef(1.f, 1.f + ex2f(-1.4426950408889634f*x));
}
__device__ __forceinline__ float tanh_f(float x){
    float r; asm("tanh.approx.f32 %0, %1;" : "=f"(r) : "f"(x)); return r;
}

// ---------------- static device scratch (no allocations) ----------------
__device__ float g_emb[NL*NB*NIN];
__device__ float g_xg[2*NL*NG*NB];          // [dir][t][g][b]
__device__ float g_hx[2*8*2*GB*256];        // [dir][grp][parity][b16][u256]
__device__ float g_hall[2*NL*NB*NH];        // [dir][t][b][256]
__device__ float g_x[NB*NL*NH];
__device__ float g_u[NB*NCAP*16];
__device__ float g_att[NB*NL];
__device__ float g_cbase[NCAP*NCL];
__device__ __nv_bfloat16 g_uhat[(size_t)NB*NCAP*NOD];   // bf16: halves routing traffic
__device__ float g_bb[(size_t)NB*NCAP*NCL];
__device__ float g_spart[NB*NCH*NOD];
__device__ float g_v[NB*NOD];
__device__ unsigned g_gcnt[16*64];          // per-group barrier counters, 256B apart

// 0) zero the group counters (separate launch -> race-free base for k_lstm)
__global__ void k_zero(){
    if(threadIdx.x<16) g_gcnt[threadIdx.x*64]=0u;
}

// 1) embedding gather
__global__ void k_embed(const int* __restrict__ word,const int* __restrict__ tag,
                        const int* __restrict__ p1,const int* __restrict__ p2,
                        const float* __restrict__ we,const float* __restrict__ te,
                        const float* __restrict__ p1e,const float* __restrict__ p2e){
    int bl=blockIdx.x, t=bl/NB, b=bl%NB, d=threadIdx.x;
    float v;
    if(d<100)      v=we[(size_t)word[b*NL+t]*100+d];
    else if(d<120) v=te[tag[b*NL+t]*20+(d-100)];
    else if(d<140) v=p1e[p1[b*NL+t]*20+(d-120)];
    else           v=p2e[p2[b*NL+t]*20+(d-140)];
    g_emb[(t*NB+b)*NIN+d]=v;
}

// 2) xg = emb @ w_ih^T + b_ih + b_hh  -> [dir][t][g][b]   (R5 scalar version, known good)
__global__ __launch_bounds__(256) void k_xg(
        const float* __restrict__ wih_f,const float* __restrict__ wih_b,
        const float* __restrict__ bih_f,const float* __restrict__ bhh_f,
        const float* __restrict__ bih_b,const float* __restrict__ bhh_b){
    __shared__ float Ws[64*17];
    __shared__ float Es[64*17];
    int t=blockIdx.y, dir=blockIdx.z;
    int g0=(blockIdx.x&15)*64, b0=(blockIdx.x>>4)*64;
    const float* wih=dir?wih_b:wih_f;
    const float* bih=dir?bih_b:bih_f;
    const float* bhh=dir?bhh_b:bhh_f;
    int tid=threadIdx.x, tx=tid&15, ty=tid>>4;
    float acc[4][4];
    #pragma unroll
    for(int i=0;i<4;i++)
        #pragma unroll
        for(int j=0;j<4;j++) acc[i][j]=0.f;
    for(int kk=0;kk<NIN;kk+=16){
        #pragma unroll
        for(int e=tid;e<1024;e+=256){
            int r=e>>4,c=e&15;
            Ws[r*17+c]=wih[(g0+r)*NIN+kk+c];
            Es[r*17+c]=g_emb[(t*NB+b0+r)*NIN+kk+c];
        }
        __syncthreads();
        #pragma unroll
        for(int k=0;k<16;k++){
            float a[4],eb[4];
            #pragma unroll
            for(int i=0;i<4;i++) a[i]=Ws[(ty*4+i)*17+k];
            #pragma unroll
            for(int j=0;j<4;j++) eb[j]=Es[(tx*4+j)*17+k];
            #pragma unroll
            for(int i=0;i<4;i++)
                #pragma unroll
                for(int j=0;j<4;j++) acc[i][j]+=a[i]*eb[j];
        }
        __syncthreads();
    }
    #pragma unroll
    for(int i=0;i<4;i++){
        int g=g0+ty*4+i;
        float bias=bih[g]+bhh[g];
        float4 r4=make_float4(acc[i][0]+bias,acc[i][1]+bias,acc[i][2]+bias,acc[i][3]+bias);
        *(float4*)(g_xg+((size_t)(dir*NL+t)*NG+g)*NB+b0+tx*4)=r4;
    }
}

// 3) persistent BiLSTM, group-local sync (R9 structure: best measured).
__global__ __launch_bounds__(256,1) void k_lstm(const float* __restrict__ whh_f,
                                                const float* __restrict__ whh_b){
    extern __shared__ float sm[];
    float* sW=sm;               // [lrow 0..127][k 0..255], lrow=gate*32+ul
    float* sH=sm+32768;         // [b 0..15][260]
    int tid=threadIdx.x, bid=blockIdx.x;
    int dir=bid>>6, grp=(bid>>3)&7, c=bid&7;
    int gid=dir*8+grp;
    const float* whh=dir?whh_b:whh_f;
    for(int e4=tid;e4<8192;e4+=256){
        int lrow=e4>>6, k4=(e4&63)*4;
        *(float4*)(sW+lrow*256+k4)=
            *(const float4*)(whh+(size_t)((lrow>>5)*256 + c*32 + (lrow&31))*256 + k4);
    }
    __syncthreads();
    int b=tid&15, usub=tid>>4;
    int bg=grp*GB+b;
    int u0=c*32+usub*2;
    float cst[2]={0.f,0.f};
    float* hxbase=g_hx+(size_t)gid*2*GB*256;    // [parity][b][u]
    unsigned* cnt=&g_gcnt[gid*64];
    const float* wbase=sW+usub*512;
    float xr[8];
    {
        int t0=dir?(NL-1):0;
        const float* xgp=g_xg+((size_t)(dir*NL+t0)*NG)*NB;
        #pragma unroll
        for(int r=0;r<8;r++){
            int g=(r>>1)*256 + u0 + (r&1);
            xr[r]=__ldcg(xgp+(size_t)g*NB+bg);
        }
    }
    for(int s=0;s<NL;s++){
        int t=dir?(NL-1-s):s;
        ull acc2[8]={0,0,0,0,0,0,0,0};
        if(s>0){
            const float* src=hxbase+(size_t)(s&1)*GB*256;
            for(int i4=tid;i4<1024;i4+=256){
                int bb=i4>>6, k4=(i4&63)*4;
                float4 v=__ldcg((const float4*)(src+bb*256+k4));
                *(float4*)(sH+bb*260+k4)=v;
            }
            __syncthreads();
            const float* hrow=sH+b*260;
            #pragma unroll 4
            for(int k=0;k<256;k+=4){
                ulonglong2 h2=*(const ulonglong2*)(hrow+k);
                #pragma unroll
                for(int r=0;r<8;r++){
                    const ulonglong2* w2=(const ulonglong2*)(wbase+(r>>1)*8192+(r&1)*256+k);
                    FMA2(acc2[r],h2.x,w2->x);
                    FMA2(acc2[r],h2.y,w2->y);
                }
            }
        }
        float acc[8];
        #pragma unroll
        for(int r=0;r<8;r++) acc[r]=unpack_sum(acc2[r])+xr[r];
        float* hw=hxbase+(size_t)((s+1)&1)*GB*256;
        float* hall=g_hall+((size_t)(dir*NL+t)*NB+bg)*NH;
        float hn[2];
        #pragma unroll
        for(int j=0;j<2;j++){
            float cn=sigm_f(acc[2+j])*cst[j]+sigm_f(acc[j])*tanh_f(acc[4+j]);
            cst[j]=cn;
            hn[j]=sigm_f(acc[6+j])*tanh_f(cn);
        }
        *(float2*)(hw+b*256+u0)=make_float2(hn[0],hn[1]);
        *(float2*)(hall+u0)=make_float2(hn[0],hn[1]);
        if(s<NL-1){
            int tn=dir?(NL-2-s):(s+1);
            const float* xgp=g_xg+((size_t)(dir*NL+tn)*NG)*NB;
            #pragma unroll
            for(int r=0;r<8;r++){
                int g=(r>>1)*256 + u0 + (r&1);
                xr[r]=__ldcg(xgp+(size_t)g*NB+bg);
            }
        }
        __threadfence();
        __syncthreads();
        if(tid==0){
            atomicAdd(cnt,1u);
            if(s<NL-1){
                unsigned tgt=(unsigned)(GSZ*(s+1));
                while(*((volatile unsigned*)cnt)<tgt) __nanosleep(32);
            }
        }
        __syncthreads();
        __threadfence();
    }
}

// 4) x = hf + hb ; u = squash(primary caps)
__global__ __launch_bounds__(256) void k_combine(){
    int bl=blockIdx.x, b=bl/NL, l=bl%NL, j=threadIdx.x;
    float v=g_hall[((size_t)(0*NL+l)*NB+b)*NH+j]+g_hall[((size_t)(1*NL+l)*NB+b)*NH+j];
    g_x[((size_t)b*NL+l)*NH+j]=v;
    float n2=v*v;
    n2+=__shfl_xor_sync(0xffffffffu,n2,1);
    n2+=__shfl_xor_sync(0xffffffffu,n2,2);
    n2+=__shfl_xor_sync(0xffffffffu,n2,4);
    n2+=__shfl_xor_sync(0xffffffffu,n2,8);
    float f=(n2/(1.f+n2))*rsqrtf(n2+1e-9f);
    g_u[((size_t)b*NCAP+l*16)*16+j]=v*f;
}

// 5) entity gather + attention softmax over L
__global__ __launch_bounds__(256) void k_att(const int* __restrict__ pos1,
                                             const int* __restrict__ pos2){
    __shared__ int se1,se2;
    __shared__ float she[NH];
    __shared__ float sd[NL];
    int b=blockIdx.x, tid=threadIdx.x;
    if(tid<NL){
        if(pos1[b*NL+tid]==68) se1=tid;
        if(pos2[b*NL+tid]==68) se2=tid;
    }
    __syncthreads();
    she[tid]=g_x[((size_t)b*NL+se1)*NH+tid]+g_x[((size_t)b*NL+se2)*NH+tid];
    __syncthreads();
    int warp=tid>>5, lane=tid&31;
    for(int l=warp;l<NL;l+=8){
        const float* xr=g_x+((size_t)b*NL+l)*NH;
        float s=0.f;
        for(int k=lane;k<NH;k+=32) s+=xr[k]*she[k];
        for(int m=16;m;m>>=1) s+=__shfl_xor_sync(0xffffffffu,s,m);
        if(lane==0) sd[l]=s;
    }
    __syncthreads();
    if(tid<32){
        float vals[4],mx=-1e30f;
        #pragma unroll
        for(int q=0;q<4;q++){
            int l=tid+32*q;
            vals[q]=(l<NL)?sd[l]:-1e30f;
            mx=fmaxf(mx,vals[q]);
        }
        for(int m=16;m;m>>=1) mx=fmaxf(mx,__shfl_xor_sync(0xffffffffu,mx,m));
        float es[4],ss=0.f;
        #pragma unroll
        for(int q=0;q<4;q++){
            int l=tid+32*q;
            es[q]=(l<NL)?expf(vals[q]-mx):0.f;
            ss+=es[q];
        }
        for(int m=16;m;m>>=1) ss+=__shfl_xor_sync(0xffffffffu,ss,m);
        float inv=1.f/ss;
        #pragma unroll
        for(int q=0;q<4;q++){
            int l=tid+32*q;
            if(l<NL) g_att[b*NL+l]=es[q]*inv;
        }
    }
}

// 6) softmax(b_route) once
__global__ void k_cbase(const float* __restrict__ br){
    int i=blockIdx.x, lane=threadIdx.x;
    float v=(lane<NCL)?br[i*NCL+lane]:-1e30f;
    float mx=v;
    for(int m=16;m;m>>=1) mx=fmaxf(mx,__shfl_xor_sync(0xffffffffu,mx,m));
    float e=(lane<NCL)?expf(v-mx):0.f;
    float s=e;
    for(int m=16;m;m>>=1) s+=__shfl_xor_sync(0xffffffffu,s,m);
    if(lane<NCL) g_cbase[i*NCL+lane]=e/s;
}

// 7) u_hat[b][i][:] = u[b][i][:16] @ W_caps[i]  -> bf16 output
__global__ __launch_bounds__(256) void k_uhat(const float* __restrict__ Wc){
    __shared__ float Ws[16*NOD];
    __shared__ float Ut[16*132];
    int i=blockIdx.x, tid=threadIdx.x;
    const float* wp=Wc+(size_t)i*16*NOD;
    for(int e=tid;e<16*NOD;e+=256) Ws[e]=wp[e];
    for(int e=tid;e<2048;e+=256){
        int bb_=e>>4,cc=e&15;
        Ut[cc*132+bb_]=g_u[((size_t)bb_*NCAP+i)*16+cc];
    }
    __syncthreads();
    for(int tI=tid;tI<32*76;tI+=256){
        int ot=tI%76, bt=tI/76, o0=ot*4, b0=bt*4;
        float acc[4][4];
        #pragma unroll
        for(int x=0;x<4;x++)
            #pragma unroll
            for(int y=0;y<4;y++) acc[x][y]=0.f;
        #pragma unroll
        for(int cc=0;cc<16;cc++){
            float4 u4=*(const float4*)(Ut+cc*132+b0);
            float4 w4=*(const float4*)(Ws+cc*NOD+o0);
            acc[0][0]+=u4.x*w4.x; acc[0][1]+=u4.x*w4.y; acc[0][2]+=u4.x*w4.z; acc[0][3]+=u4.x*w4.w;
            acc[1][0]+=u4.y*w4.x; acc[1][1]+=u4.y*w4.y; acc[1][2]+=u4.y*w4.z; acc[1][3]+=u4.y*w4.w;
            acc[2][0]+=u4.z*w4.x; acc[2][1]+=u4.z*w4.y; acc[2][2]+=u4.z*w4.z; acc[2][3]+=u4.z*w4.w;
            acc[3][0]+=u4.w*w4.x; acc[3][1]+=u4.w*w4.y; acc[3][2]+=u4.w*w4.z; acc[3][3]+=u4.w*w4.w;
        }
        #pragma unroll
        for(int bi=0;bi<4;bi++){
            uint2 p;
            p.x=pack_bf16x2(acc[bi][0],acc[bi][1]);
            p.y=pack_bf16x2(acc[bi][2],acc[bi][3]);
            *(uint2*)(g_uhat+((size_t)(b0+bi)*NCAP+i)*NOD+o0)=p;
        }
    }
}

// 8) fused routing pass (bf16 u_hat reads)
__global__ __launch_bounds__(320) void k_route(int mode,const float* __restrict__ b_route){
    __shared__ float sv[320];
    __shared__ float sag[32];
    __shared__ float sc[32];
    int tid=threadIdx.x, b=blockIdx.y, chunk=blockIdx.x;
    int o=tid>>4, d=tid&15;
    sv[tid]=(mode>0&&tid<NOD)?g_v[b*NOD+tid]:0.f;
    __syncthreads();
    int i0=chunk*(NCAP/NCH);
    float accS=0.f;
    float u=(tid<NOD)?__bfloat162float(g_uhat[((size_t)b*NCAP+i0)*NOD+tid]):0.f;
    for(int ii=0;ii<NCAP/NCH;ii++){
        int i=i0+ii;
        float unext=0.f;
        if(ii+1<NCAP/NCH&&tid<NOD)
            unext=__bfloat162float(g_uhat[((size_t)b*NCAP+i+1)*NOD+tid]);
        float atti=g_att[b*NL+(i>>4)];
        float cO;
        if(mode==0){
            cO=(o<NCL)?g_cbase[i*NCL+o]*atti:0.f;
        } else {
            float p=u*sv[tid];
            p+=__shfl_xor_sync(0xffffffffu,p,1);
            p+=__shfl_xor_sync(0xffffffffu,p,2);
            p+=__shfl_xor_sync(0xffffffffu,p,4);
            p+=__shfl_xor_sync(0xffffffffu,p,8);
            if(d==0&&o<NCL){
                float prior=(mode==1)?b_route[i*NCL+o]:g_bb[((size_t)b*NCAP+i)*NCL+o];
                float nb=prior+p;
                if(mode==1) g_bb[((size_t)b*NCAP+i)*NCL+o]=nb;
                sag[o]=nb;
            }
            __syncthreads();
            if(tid<32){
                float v=(tid<NCL)?sag[tid]:-1e30f;
                float mx=v;
                for(int m=16;m;m>>=1) mx=fmaxf(mx,__shfl_xor_sync(0xffffffffu,mx,m));
                float e=(tid<NCL)?expf(v-mx):0.f;
                float ss=e;
                for(int m=16;m;m>>=1) ss+=__shfl_xor_sync(0xffffffffu,ss,m);
                if(tid<NCL) sc[tid]=e/ss*atti;
            }
            __syncthreads();
            cO=(o<NCL)?sc[o]:0.f;
        }
        accS+=cO*u;
        u=unext;
    }
    if(tid<NOD) g_spart[(b*NCH+chunk)*NOD+tid]=accS;
}

// 9) reduce partials + squash -> v (or final class lengths)
__global__ __launch_bounds__(320) void k_reduce(int final_out,float* __restrict__ out){
    int b=blockIdx.x, tid=threadIdx.x;
    float s=0.f;
    if(tid<NOD){
        #pragma unroll
        for(int ch=0;ch<NCH;ch++) s+=g_spart[(b*NCH+ch)*NOD+tid];
    }
    float n2=s*s;
    n2+=__shfl_xor_sync(0xffffffffu,n2,1);
    n2+=__shfl_xor_sync(0xffffffffu,n2,2);
    n2+=__shfl_xor_sync(0xffffffffu,n2,4);
    n2+=__shfl_xor_sync(0xffffffffu,n2,8);
    float f=(n2/(1.f+n2))*rsqrtf(n2+1e-9f);
    if(!final_out){
        if(tid<NOD) g_v[b*NOD+tid]=s*f;
    } else {
        if(tid<NOD&&(tid&15)==0)
            out[b*NCL+(tid>>4)]=sqrtf(n2*f*f+1e-9f);
    }
}

extern "C" void kernel_launch(void* const* d_in,const int* in_sizes,int n_in,
                              void* d_out,int out_size){
    (void)in_sizes;(void)n_in;(void)out_size;
    const int*   word =(const int*)d_in[0];
    const int*   tag  =(const int*)d_in[1];
    const int*   pos1 =(const int*)d_in[2];
    const int*   pos2 =(const int*)d_in[3];
    const float* we   =(const float*)d_in[4];
    const float* te   =(const float*)d_in[5];
    const float* p1e  =(const float*)d_in[6];
    const float* p2e  =(const float*)d_in[7];
    const float* wih_f=(const float*)d_in[8];
    const float* whh_f=(const float*)d_in[9];
    const float* bih_f=(const float*)d_in[10];
    const float* bhh_f=(const float*)d_in[11];
    const float* wih_b=(const float*)d_in[12];
    const float* whh_b=(const float*)d_in[13];
    const float* bih_b=(const float*)d_in[14];
    const float* bhh_b=(const float*)d_in[15];
    const float* Wc   =(const float*)d_in[16];
    const float* br   =(const float*)d_in[17];
    float* out=(float*)d_out;

    cudaFuncSetAttribute(k_lstm, cudaFuncAttributeMaxDynamicSharedMemorySize, LSTM_SMEM);

    k_embed<<<NL*NB,160>>>(word,tag,pos1,pos2,we,te,p1e,p2e);
    k_cbase<<<NCAP,32>>>(br);
    k_xg<<<dim3(32,NL,2),256>>>(wih_f,wih_b,bih_f,bhh_f,bih_b,bhh_b);
    k_zero<<<1,32>>>();
    k_lstm<<<128,256,LSTM_SMEM>>>(whh_f,whh_b);
    k_combine<<<NB*NL,256>>>();
    k_att<<<NB,256>>>(pos1,pos2);
    k_uhat<<<NCAP,256>>>(Wc);
    k_route<<<dim3(NCH,NB),320>>>(0,br);
    k_reduce<<<NB,320>>>(0,out);
    k_route<<<dim3(NCH,NB),320>>>(1,br);
    k_reduce<<<NB,320>>>(0,out);
    k_route<<<dim3(NCH,NB),320>>>(2,br);
    k_reduce<<<NB,320>>>(1,out);
}

// round 15
// speedup vs baseline: 1.3358x; 1.2745x over previous
#include <cuda_runtime.h>
#include <cuda_bf16.h>
#include <math.h>

#define NB 128
#define NL 100
#define NH 256
#define NIN 160
#define NG 1024
#define NCAP 1600
#define NCL 19
#define NOD 304
#define NCH 8
#define GSZ 8      // CTAs per LSTM group (hidden split)
#define GB  16     // batch rows per group
#define LSTM_SMEM (131072 + 16*260*4)

typedef unsigned long long ull;

// packed fp32x2 fma: c = a*b + c
#define FMA2(c,a,b) asm("fma.rn.f32x2 %0, %1, %2, %3;" : "=l"(c) : "l"(a), "l"(b), "l"(c))

__device__ __forceinline__ float unpack_sum(ull v){
    float lo, hi;
    asm("mov.b64 {%0,%1}, %2;" : "=f"(lo), "=f"(hi) : "l"(v));
    return lo + hi;
}

// fast activations (MUFU-based)
__device__ __forceinline__ float ex2f(float x){
    float r; asm("ex2.approx.ftz.f32 %0, %1;" : "=f"(r) : "f"(x)); return r;
}
__device__ __forceinline__ float sigm_f(float x){
    return __fdividef(1.f, 1.f + ex2f(-1.4426950408889634f*x));
}
__device__ __forceinline__ float tanh_f(float x){
    float r; asm("tanh.approx.f32 %0, %1;" : "=f"(r) : "f"(x)); return r;
}

// ---------------- static device scratch (no allocations) ----------------
__device__ float g_emb[NL*NB*NIN];
__device__ float g_xg[2*NL*NG*NB];          // [dir][t][g][b]
__device__ float g_hx[2*8*2*GB*256];        // [dir][grp][parity][b16][u256]
__device__ float g_hall[2*NL*NB*NH];        // [dir][t][b][256]
__device__ float g_x[NB*NL*NH];
__device__ float g_u[NB*NCAP*16];
__device__ float g_att[NB*NL];
__device__ float g_cbase[NCAP*NCL];
__device__ float g_uhat[(size_t)NB*NCAP*NOD];   // fp32 (bf16 measured slower)
__device__ float g_bb[(size_t)NB*NCAP*NCL];
__device__ float g_spart[NB*NCH*NOD];
__device__ float g_v[NB*NOD];
__device__ unsigned g_gcnt[16*64];          // per-group barrier counters, 256B apart

// 0) zero the group counters (separate launch -> race-free base for k_lstm)
__global__ void k_zero(){
    if(threadIdx.x<16) g_gcnt[threadIdx.x*64]=0u;
}

// 1) embedding gather
__global__ void k_embed(const int* __restrict__ word,const int* __restrict__ tag,
                        const int* __restrict__ p1,const int* __restrict__ p2,
                        const float* __restrict__ we,const float* __restrict__ te,
                        const float* __restrict__ p1e,const float* __restrict__ p2e){
    int bl=blockIdx.x, t=bl/NB, b=bl%NB, d=threadIdx.x;
    float v;
    if(d<100)      v=we[(size_t)word[b*NL+t]*100+d];
    else if(d<120) v=te[tag[b*NL+t]*20+(d-100)];
    else if(d<140) v=p1e[p1[b*NL+t]*20+(d-120)];
    else           v=p2e[p2[b*NL+t]*20+(d-140)];
    g_emb[(t*NB+b)*NIN+d]=v;
}

// 2) xg = emb @ w_ih^T + b_ih + b_hh  -> [dir][t][g][b]   (R5 scalar version, known good)
__global__ __launch_bounds__(256) void k_xg(
        const float* __restrict__ wih_f,const float* __restrict__ wih_b,
        const float* __restrict__ bih_f,const float* __restrict__ bhh_f,
        const float* __restrict__ bih_b,const float* __restrict__ bhh_b){
    __shared__ float Ws[64*17];
    __shared__ float Es[64*17];
    int t=blockIdx.y, dir=blockIdx.z;
    int g0=(blockIdx.x&15)*64, b0=(blockIdx.x>>4)*64;
    const float* wih=dir?wih_b:wih_f;
    const float* bih=dir?bih_b:bih_f;
    const float* bhh=dir?bhh_b:bhh_f;
    int tid=threadIdx.x, tx=tid&15, ty=tid>>4;
    float acc[4][4];
    #pragma unroll
    for(int i=0;i<4;i++)
        #pragma unroll
        for(int j=0;j<4;j++) acc[i][j]=0.f;
    for(int kk=0;kk<NIN;kk+=16){
        #pragma unroll
        for(int e=tid;e<1024;e+=256){
            int r=e>>4,c=e&15;
            Ws[r*17+c]=wih[(g0+r)*NIN+kk+c];
            Es[r*17+c]=g_emb[(t*NB+b0+r)*NIN+kk+c];
        }
        __syncthreads();
        #pragma unroll
        for(int k=0;k<16;k++){
            float a[4],eb[4];
            #pragma unroll
            for(int i=0;i<4;i++) a[i]=Ws[(ty*4+i)*17+k];
            #pragma unroll
            for(int j=0;j<4;j++) eb[j]=Es[(tx*4+j)*17+k];
            #pragma unroll
            for(int i=0;i<4;i++)
                #pragma unroll
                for(int j=0;j<4;j++) acc[i][j]+=a[i]*eb[j];
        }
        __syncthreads();
    }
    #pragma unroll
    for(int i=0;i<4;i++){
        int g=g0+ty*4+i;
        float bias=bih[g]+bhh[g];
        float4 r4=make_float4(acc[i][0]+bias,acc[i][1]+bias,acc[i][2]+bias,acc[i][3]+bias);
        *(float4*)(g_xg+((size_t)(dir*NL+t)*NG+g)*NB+b0+tx*4)=r4;
    }
}

// 3) persistent BiLSTM, group-local sync (R9 structure: best measured).
__global__ __launch_bounds__(256,1) void k_lstm(const float* __restrict__ whh_f,
                                                const float* __restrict__ whh_b){
    extern __shared__ float sm[];
    float* sW=sm;               // [lrow 0..127][k 0..255], lrow=gate*32+ul
    float* sH=sm+32768;         // [b 0..15][260]
    int tid=threadIdx.x, bid=blockIdx.x;
    int dir=bid>>6, grp=(bid>>3)&7, c=bid&7;
    int gid=dir*8+grp;
    const float* whh=dir?whh_b:whh_f;
    for(int e4=tid;e4<8192;e4+=256){
        int lrow=e4>>6, k4=(e4&63)*4;
        *(float4*)(sW+lrow*256+k4)=
            *(const float4*)(whh+(size_t)((lrow>>5)*256 + c*32 + (lrow&31))*256 + k4);
    }
    __syncthreads();
    int b=tid&15, usub=tid>>4;
    int bg=grp*GB+b;
    int u0=c*32+usub*2;
    float cst[2]={0.f,0.f};
    float* hxbase=g_hx+(size_t)gid*2*GB*256;    // [parity][b][u]
    unsigned* cnt=&g_gcnt[gid*64];
    const float* wbase=sW+usub*512;
    float xr[8];
    {
        int t0=dir?(NL-1):0;
        const float* xgp=g_xg+((size_t)(dir*NL+t0)*NG)*NB;
        #pragma unroll
        for(int r=0;r<8;r++){
            int g=(r>>1)*256 + u0 + (r&1);
            xr[r]=__ldcg(xgp+(size_t)g*NB+bg);
        }
    }
    for(int s=0;s<NL;s++){
        int t=dir?(NL-1-s):s;
        ull acc2[8]={0,0,0,0,0,0,0,0};
        if(s>0){
            const float* src=hxbase+(size_t)(s&1)*GB*256;
            for(int i4=tid;i4<1024;i4+=256){
                int bb=i4>>6, k4=(i4&63)*4;
                float4 v=__ldcg((const float4*)(src+bb*256+k4));
                *(float4*)(sH+bb*260+k4)=v;
            }
            __syncthreads();
            const float* hrow=sH+b*260;
            #pragma unroll 4
            for(int k=0;k<256;k+=4){
                ulonglong2 h2=*(const ulonglong2*)(hrow+k);
                #pragma unroll
                for(int r=0;r<8;r++){
                    const ulonglong2* w2=(const ulonglong2*)(wbase+(r>>1)*8192+(r&1)*256+k);
                    FMA2(acc2[r],h2.x,w2->x);
                    FMA2(acc2[r],h2.y,w2->y);
                }
            }
        }
        float acc[8];
        #pragma unroll
        for(int r=0;r<8;r++) acc[r]=unpack_sum(acc2[r])+xr[r];
        float* hw=hxbase+(size_t)((s+1)&1)*GB*256;
        float* hall=g_hall+((size_t)(dir*NL+t)*NB+bg)*NH;
        float hn[2];
        #pragma unroll
        for(int j=0;j<2;j++){
            float cn=sigm_f(acc[2+j])*cst[j]+sigm_f(acc[j])*tanh_f(acc[4+j]);
            cst[j]=cn;
            hn[j]=sigm_f(acc[6+j])*tanh_f(cn);
        }
        *(float2*)(hw+b*256+u0)=make_float2(hn[0],hn[1]);
        *(float2*)(hall+u0)=make_float2(hn[0],hn[1]);
        if(s<NL-1){
            int tn=dir?(NL-2-s):(s+1);
            const float* xgp=g_xg+((size_t)(dir*NL+tn)*NG)*NB;
            #pragma unroll
            for(int r=0;r<8;r++){
                int g=(r>>1)*256 + u0 + (r&1);
                xr[r]=__ldcg(xgp+(size_t)g*NB+bg);
            }
        }
        __threadfence();
        __syncthreads();
        if(tid==0){
            atomicAdd(cnt,1u);
            if(s<NL-1){
                unsigned tgt=(unsigned)(GSZ*(s+1));
                while(*((volatile unsigned*)cnt)<tgt) __nanosleep(32);
            }
        }
        __syncthreads();
        __threadfence();
    }
}

// 4) x = hf + hb ; u = squash(primary caps)
__global__ __launch_bounds__(256) void k_combine(){
    int bl=blockIdx.x, b=bl/NL, l=bl%NL, j=threadIdx.x;
    float v=g_hall[((size_t)(0*NL+l)*NB+b)*NH+j]+g_hall[((size_t)(1*NL+l)*NB+b)*NH+j];
    g_x[((size_t)b*NL+l)*NH+j]=v;
    float n2=v*v;
    n2+=__shfl_xor_sync(0xffffffffu,n2,1);
    n2+=__shfl_xor_sync(0xffffffffu,n2,2);
    n2+=__shfl_xor_sync(0xffffffffu,n2,4);
    n2+=__shfl_xor_sync(0xffffffffu,n2,8);
    float f=(n2/(1.f+n2))*rsqrtf(n2+1e-9f);
    g_u[((size_t)b*NCAP+l*16)*16+j]=v*f;
}

// 5) entity gather + attention softmax over L
__global__ __launch_bounds__(256) void k_att(const int* __restrict__ pos1,
                                             const int* __restrict__ pos2){
    __shared__ int se1,se2;
    __shared__ float she[NH];
    __shared__ float sd[NL];
    int b=blockIdx.x, tid=threadIdx.x;
    if(tid<NL){
        if(pos1[b*NL+tid]==68) se1=tid;
        if(pos2[b*NL+tid]==68) se2=tid;
    }
    __syncthreads();
    she[tid]=g_x[((size_t)b*NL+se1)*NH+tid]+g_x[((size_t)b*NL+se2)*NH+tid];
    __syncthreads();
    int warp=tid>>5, lane=tid&31;
    for(int l=warp;l<NL;l+=8){
        const float* xr=g_x+((size_t)b*NL+l)*NH;
        float s=0.f;
        for(int k=lane;k<NH;k+=32) s+=xr[k]*she[k];
        for(int m=16;m;m>>=1) s+=__shfl_xor_sync(0xffffffffu,s,m);
        if(lane==0) sd[l]=s;
    }
    __syncthreads();
    if(tid<32){
        float vals[4],mx=-1e30f;
        #pragma unroll
        for(int q=0;q<4;q++){
            int l=tid+32*q;
            vals[q]=(l<NL)?sd[l]:-1e30f;
            mx=fmaxf(mx,vals[q]);
        }
        for(int m=16;m;m>>=1) mx=fmaxf(mx,__shfl_xor_sync(0xffffffffu,mx,m));
        float es[4],ss=0.f;
        #pragma unroll
        for(int q=0;q<4;q++){
            int l=tid+32*q;
            es[q]=(l<NL)?expf(vals[q]-mx):0.f;
            ss+=es[q];
        }
        for(int m=16;m;m>>=1) ss+=__shfl_xor_sync(0xffffffffu,ss,m);
        float inv=1.f/ss;
        #pragma unroll
        for(int q=0;q<4;q++){
            int l=tid+32*q;
            if(l<NL) g_att[b*NL+l]=es[q]*inv;
        }
    }
}

// 6) softmax(b_route) once
__global__ void k_cbase(const float* __restrict__ br){
    int i=blockIdx.x, lane=threadIdx.x;
    float v=(lane<NCL)?br[i*NCL+lane]:-1e30f;
    float mx=v;
    for(int m=16;m;m>>=1) mx=fmaxf(mx,__shfl_xor_sync(0xffffffffu,mx,m));
    float e=(lane<NCL)?expf(v-mx):0.f;
    float s=e;
    for(int m=16;m;m>>=1) s+=__shfl_xor_sync(0xffffffffu,s,m);
    if(lane<NCL) g_cbase[i*NCL+lane]=e/s;
}

// 7) u_hat[b][i][:] = u[b][i][:16] @ W_caps[i]  -> fp32 output
__global__ __launch_bounds__(256) void k_uhat(const float* __restrict__ Wc){
    __shared__ float Ws[16*NOD];
    __shared__ float Ut[16*132];
    int i=blockIdx.x, tid=threadIdx.x;
    const float* wp=Wc+(size_t)i*16*NOD;
    for(int e=tid;e<16*NOD;e+=256) Ws[e]=wp[e];
    for(int e=tid;e<2048;e+=256){
        int bb_=e>>4,cc=e&15;
        Ut[cc*132+bb_]=g_u[((size_t)bb_*NCAP+i)*16+cc];
    }
    __syncthreads();
    for(int tI=tid;tI<32*76;tI+=256){
        int ot=tI%76, bt=tI/76, o0=ot*4, b0=bt*4;
        float acc[4][4];
        #pragma unroll
        for(int x=0;x<4;x++)
            #pragma unroll
            for(int y=0;y<4;y++) acc[x][y]=0.f;
        #pragma unroll
        for(int cc=0;cc<16;cc++){
            float4 u4=*(const float4*)(Ut+cc*132+b0);
            float4 w4=*(const float4*)(Ws+cc*NOD+o0);
            acc[0][0]+=u4.x*w4.x; acc[0][1]+=u4.x*w4.y; acc[0][2]+=u4.x*w4.z; acc[0][3]+=u4.x*w4.w;
            acc[1][0]+=u4.y*w4.x; acc[1][1]+=u4.y*w4.y; acc[1][2]+=u4.y*w4.z; acc[1][3]+=u4.y*w4.w;
            acc[2][0]+=u4.z*w4.x; acc[2][1]+=u4.z*w4.y; acc[2][2]+=u4.z*w4.z; acc[2][3]+=u4.z*w4.w;
            acc[3][0]+=u4.w*w4.x; acc[3][1]+=u4.w*w4.y; acc[3][2]+=u4.w*w4.z; acc[3][3]+=u4.w*w4.w;
        }
        #pragma unroll
        for(int bi=0;bi<4;bi++){
            float4 r4=make_float4(acc[bi][0],acc[bi][1],acc[bi][2],acc[bi][3]);
            *(float4*)(g_uhat+((size_t)(b0+bi)*NCAP+i)*NOD+o0)=r4;
        }
    }
}

// 8) warp-autonomous fused routing pass: NO block barriers.
//    One warp = (b, chunk of 200 capsules). lane = output class o (19 active).
//    Per capsule: lane o loads its 16-d u_hat slice, agreement p = u.v (regs),
//    softmax over classes = one 5-step shfl butterfly, accumulate s in regs.
__global__ __launch_bounds__(256) void k_route(int mode,const float* __restrict__ b_route){
    int b=blockIdx.x;
    int w=threadIdx.x>>5, lane=threadIdx.x&31;
    int o=lane;
    bool act=(lane<NCL);
    float vd[16];
    if(mode>0){
        #pragma unroll
        for(int q=0;q<4;q++){
            float4 t=act?*(const float4*)(g_v+b*NOD+o*16+q*4):make_float4(0,0,0,0);
            vd[q*4+0]=t.x; vd[q*4+1]=t.y; vd[q*4+2]=t.z; vd[q*4+3]=t.w;
        }
    }
    float sacc[16];
    #pragma unroll
    for(int d=0;d<16;d++) sacc[d]=0.f;
    const int i0=w*(NCAP/NCH);
    // prefetch first capsule's u slice
    float u[16];
    {
        const float* up=g_uhat+((size_t)b*NCAP+i0)*NOD+o*16;
        #pragma unroll
        for(int q=0;q<4;q++){
            float4 t=act?__ldcg((const float4*)(up+q*4)):make_float4(0,0,0,0);
            u[q*4+0]=t.x; u[q*4+1]=t.y; u[q*4+2]=t.z; u[q*4+3]=t.w;
        }
    }
    for(int ii=0;ii<NCAP/NCH;ii++){
        int i=i0+ii;
        // prefetch next capsule
        float un[16];
        if(ii+1<NCAP/NCH){
            const float* up=g_uhat+((size_t)b*NCAP+i+1)*NOD+o*16;
            #pragma unroll
            for(int q=0;q<4;q++){
                float4 t=act?__ldcg((const float4*)(up+q*4)):make_float4(0,0,0,0);
                un[q*4+0]=t.x; un[q*4+1]=t.y; un[q*4+2]=t.z; un[q*4+3]=t.w;
            }
        }
        float atti=g_att[b*NL+(i>>4)];
        float c;
        if(mode==0){
            c=act?g_cbase[i*NCL+o]*atti:0.f;
        } else {
            float p=0.f;
            #pragma unroll
            for(int d=0;d<16;d++) p+=u[d]*vd[d];
            float nb=0.f;
            if(act){
                float prior=(mode==1)?b_route[i*NCL+o]:g_bb[((size_t)b*NCAP+i)*NCL+o];
                nb=prior+p;
                if(mode==1) g_bb[((size_t)b*NCAP+i)*NCL+o]=nb;
            }
            // softmax over classes within the warp (no max-shift: values are O(1))
            float e=act?ex2f(1.4426950408889634f*nb):0.f;
            float ss=e;
            ss+=__shfl_xor_sync(0xffffffffu,ss,1);
            ss+=__shfl_xor_sync(0xffffffffu,ss,2);
            ss+=__shfl_xor_sync(0xffffffffu,ss,4);
            ss+=__shfl_xor_sync(0xffffffffu,ss,8);
            ss+=__shfl_xor_sync(0xffffffffu,ss,16);
            c=act?__fdividef(e,ss)*atti:0.f;
        }
        #pragma unroll
        for(int d=0;d<16;d++) sacc[d]+=c*u[d];
        #pragma unroll
        for(int d=0;d<16;d++) u[d]=un[d];
    }
    if(act){
        float* sp=g_spart+((size_t)b*NCH+w)*NOD+o*16;
        #pragma unroll
        for(int q=0;q<4;q++)
            *(float4*)(sp+q*4)=make_float4(sacc[q*4+0],sacc[q*4+1],sacc[q*4+2],sacc[q*4+3]);
    }
}

// 9) reduce partials + squash -> v (or final class lengths)
__global__ __launch_bounds__(320) void k_reduce(int final_out,float* __restrict__ out){
    int b=blockIdx.x, tid=threadIdx.x;
    float s=0.f;
    if(tid<NOD){
        #pragma unroll
        for(int ch=0;ch<NCH;ch++) s+=g_spart[((size_t)b*NCH+ch)*NOD+tid];
    }
    float n2=s*s;
    n2+=__shfl_xor_sync(0xffffffffu,n2,1);
    n2+=__shfl_xor_sync(0xffffffffu,n2,2);
    n2+=__shfl_xor_sync(0xffffffffu,n2,4);
    n2+=__shfl_xor_sync(0xffffffffu,n2,8);
    float f=(n2/(1.f+n2))*rsqrtf(n2+1e-9f);
    if(!final_out){
        if(tid<NOD) g_v[b*NOD+tid]=s*f;
    } else {
        if(tid<NOD&&(tid&15)==0)
            out[b*NCL+(tid>>4)]=sqrtf(n2*f*f+1e-9f);
    }
}

extern "C" void kernel_launch(void* const* d_in,const int* in_sizes,int n_in,
                              void* d_out,int out_size){
    (void)in_sizes;(void)n_in;(void)out_size;
    const int*   word =(const int*)d_in[0];
    const int*   tag  =(const int*)d_in[1];
    const int*   pos1 =(const int*)d_in[2];
    const int*   pos2 =(const int*)d_in[3];
    const float* we   =(const float*)d_in[4];
    const float* te   =(const float*)d_in[5];
    const float* p1e  =(const float*)d_in[6];
    const float* p2e  =(const float*)d_in[7];
    const float* wih_f=(const float*)d_in[8];
    const float* whh_f=(const float*)d_in[9];
    const float* bih_f=(const float*)d_in[10];
    const float* bhh_f=(const float*)d_in[11];
    const float* wih_b=(const float*)d_in[12];
    const float* whh_b=(const float*)d_in[13];
    const float* bih_b=(const float*)d_in[14];
    const float* bhh_b=(const float*)d_in[15];
    const float* Wc   =(const float*)d_in[16];
    const float* br   =(const float*)d_in[17];
    float* out=(float*)d_out;

    cudaFuncSetAttribute(k_lstm, cudaFuncAttributeMaxDynamicSharedMemorySize, LSTM_SMEM);

    k_embed<<<NL*NB,160>>>(word,tag,pos1,pos2,we,te,p1e,p2e);
    k_cbase<<<NCAP,32>>>(br);
    k_xg<<<dim3(32,NL,2),256>>>(wih_f,wih_b,bih_f,bhh_f,bih_b,bhh_b);
    k_zero<<<1,32>>>();
    k_lstm<<<128,256,LSTM_SMEM>>>(whh_f,whh_b);
    k_combine<<<NB*NL,256>>>();
    k_att<<<NB,256>>>(pos1,pos2);
    k_uhat<<<NCAP,256>>>(Wc);
    k_route<<<NB,256>>>(0,br);
    k_reduce<<<NB,320>>>(0,out);
    k_route<<<NB,256>>>(1,br);
    k_reduce<<<NB,320>>>(0,out);
    k_route<<<NB,256>>>(2,br);
    k_reduce<<<NB,320>>>(1,out);
}

// round 17
// speedup vs baseline: 1.5662x; 1.1725x over previous
#include <cuda_runtime.h>
#include <cuda_bf16.h>
#include <math.h>

#define NB 128
#define NL 100
#define NH 256
#define NIN 160
#define NG 1024
#define NCAP 1600
#define NCL 19
#define NOD 304
#define NCH 8
#define GSZ 8      // CTAs per LSTM group (hidden split)
#define GB  16     // batch rows per group
#define LSTM_SMEM (131072 + 16*260*4)

typedef unsigned long long ull;

// packed fp32x2 fma: c = a*b + c
#define FMA2(c,a,b) asm("fma.rn.f32x2 %0, %1, %2, %3;" : "=l"(c) : "l"(a), "l"(b), "l"(c))

__device__ __forceinline__ float unpack_sum(ull v){
    float lo, hi;
    asm("mov.b64 {%0,%1}, %2;" : "=f"(lo), "=f"(hi) : "l"(v));
    return lo + hi;
}

// fast activations (MUFU-based)
__device__ __forceinline__ float ex2f(float x){
    float r; asm("ex2.approx.ftz.f32 %0, %1;" : "=f"(r) : "f"(x)); return r;
}
__device__ __forceinline__ float sigm_f(float x){
    return __fdividef(1.f, 1.f + ex2f(-1.4426950408889634f*x));
}
__device__ __forceinline__ float tanh_f(float x){
    float r; asm("tanh.approx.f32 %0, %1;" : "=f"(r) : "f"(x)); return r;
}

// scoped barrier primitives (replace threadfence + plain atomic + volatile poll)
__device__ __forceinline__ void red_release_add(unsigned* p, unsigned v){
    asm volatile("red.release.gpu.global.add.u32 [%0], %1;" :: "l"(p), "r"(v) : "memory");
}
__device__ __forceinline__ unsigned ld_acquire(unsigned* p){
    unsigned v;
    asm volatile("ld.acquire.gpu.global.u32 %0, [%1];" : "=r"(v) : "l"(p) : "memory");
    return v;
}

// ---------------- static device scratch (no allocations) ----------------
__device__ float g_emb[NL*NB*NIN];
__device__ float g_xg[2*NL*NG*NB];          // [dir][t][g][b]
__device__ float g_hx[2*8*2*GB*256];        // [dir][grp][parity][b16][u256]
__device__ float g_hall[2*NL*NB*NH];        // [dir][t][b][256]
__device__ float g_x[NB*NL*NH];
__device__ float g_u[NB*NCAP*16];
__device__ float g_att[NB*NL];
__device__ float g_cbase[NCAP*NCL];
__device__ float g_uhat[(size_t)NB*NCAP*NOD];   // fp32 (bf16 measured slower)
__device__ float g_bb[(size_t)NB*NCAP*NCL];
__device__ float g_spart[NB*NCH*NOD];
__device__ float g_v[NB*NOD];
__device__ unsigned g_gcnt[16*64];          // per-group barrier counters, 256B apart

// 0) zero the group counters (separate launch -> race-free base for k_lstm)
__global__ void k_zero(){
    if(threadIdx.x<16) g_gcnt[threadIdx.x*64]=0u;
}

// 1) embedding gather
__global__ void k_embed(const int* __restrict__ word,const int* __restrict__ tag,
                        const int* __restrict__ p1,const int* __restrict__ p2,
                        const float* __restrict__ we,const float* __restrict__ te,
                        const float* __restrict__ p1e,const float* __restrict__ p2e){
    int bl=blockIdx.x, t=bl/NB, b=bl%NB, d=threadIdx.x;
    float v;
    if(d<100)      v=we[(size_t)word[b*NL+t]*100+d];
    else if(d<120) v=te[tag[b*NL+t]*20+(d-100)];
    else if(d<140) v=p1e[p1[b*NL+t]*20+(d-120)];
    else           v=p2e[p2[b*NL+t]*20+(d-140)];
    g_emb[(t*NB+b)*NIN+d]=v;
}

// 2) xg = emb @ w_ih^T + b_ih + b_hh  -> [dir][t][g][b]
//    Transposed SMEM [k][row], stride 68: both operands LDS.128, conflict-free reads.
__global__ __launch_bounds__(256) void k_xg(
        const float* __restrict__ wih_f,const float* __restrict__ wih_b,
        const float* __restrict__ bih_f,const float* __restrict__ bhh_f,
        const float* __restrict__ bih_b,const float* __restrict__ bhh_b){
    __shared__ __align__(16) float Ws[16*68];   // [k][g] stride 68
    __shared__ __align__(16) float Es[16*68];   // [k][b] stride 68
    int t=blockIdx.y, dir=blockIdx.z;
    int g0=(blockIdx.x&15)*64, b0=(blockIdx.x>>4)*64;
    const float* wih=dir?wih_b:wih_f;
    const float* bih=dir?bih_b:bih_f;
    const float* bhh=dir?bhh_b:bhh_f;
    int tid=threadIdx.x, tx=tid&15, ty=tid>>4;
    float acc[4][4];
    #pragma unroll
    for(int i=0;i<4;i++)
        #pragma unroll
        for(int j=0;j<4;j++) acc[i][j]=0.f;
    for(int kk=0;kk<NIN;kk+=16){
        #pragma unroll
        for(int e=tid;e<1024;e+=256){
            int r=e>>4,c=e&15;
            Ws[c*68+r]=wih[(g0+r)*NIN+kk+c];
            Es[c*68+r]=g_emb[(t*NB+b0+r)*NIN+kk+c];
        }
        __syncthreads();
        #pragma unroll
        for(int k=0;k<16;k++){
            float4 a4=*(const float4*)(Ws+k*68+ty*4);   // broadcast (2 addrs/warp)
            float4 e4=*(const float4*)(Es+k*68+tx*4);   // contiguous, conflict-free
            float a[4]={a4.x,a4.y,a4.z,a4.w};
            float eb[4]={e4.x,e4.y,e4.z,e4.w};
            #pragma unroll
            for(int i=0;i<4;i++)
                #pragma unroll
                for(int j=0;j<4;j++) acc[i][j]+=a[i]*eb[j];
        }
        __syncthreads();
    }
    #pragma unroll
    for(int i=0;i<4;i++){
        int g=g0+ty*4+i;
        float bias=bih[g]+bhh[g];
        float4 r4=make_float4(acc[i][0]+bias,acc[i][1]+bias,acc[i][2]+bias,acc[i][3]+bias);
        *(float4*)(g_xg+((size_t)(dir*NL+t)*NG+g)*NB+b0+tx*4)=r4;
    }
}

// 3) persistent BiLSTM, group-local sync; release/acquire barrier (no threadfences).
__global__ __launch_bounds__(256,1) void k_lstm(const float* __restrict__ whh_f,
                                                const float* __restrict__ whh_b){
    extern __shared__ float sm[];
    float* sW=sm;               // [lrow 0..127][k 0..255], lrow=gate*32+ul
    float* sH=sm+32768;         // [b 0..15][260]
    int tid=threadIdx.x, bid=blockIdx.x;
    int dir=bid>>6, grp=(bid>>3)&7, c=bid&7;
    int gid=dir*8+grp;
    const float* whh=dir?whh_b:whh_f;
    for(int e4=tid;e4<8192;e4+=256){
        int lrow=e4>>6, k4=(e4&63)*4;
        *(float4*)(sW+lrow*256+k4)=
            *(const float4*)(whh+(size_t)((lrow>>5)*256 + c*32 + (lrow&31))*256 + k4);
    }
    __syncthreads();
    int b=tid&15, usub=tid>>4;
    int bg=grp*GB+b;
    int u0=c*32+usub*2;
    float cst[2]={0.f,0.f};
    float* hxbase=g_hx+(size_t)gid*2*GB*256;    // [parity][b][u]
    unsigned* cnt=&g_gcnt[gid*64];
    const float* wbase=sW+usub*512;
    float xr[8];
    {
        int t0=dir?(NL-1):0;
        const float* xgp=g_xg+((size_t)(dir*NL+t0)*NG)*NB;
        #pragma unroll
        for(int r=0;r<8;r++){
            int g=(r>>1)*256 + u0 + (r&1);
            xr[r]=__ldcg(xgp+(size_t)g*NB+bg);
        }
    }
    for(int s=0;s<NL;s++){
        int t=dir?(NL-1-s):s;
        ull acc2[8]={0,0,0,0,0,0,0,0};
        if(s>0){
            const float* src=hxbase+(size_t)(s&1)*GB*256;
            for(int i4=tid;i4<1024;i4+=256){
                int bb=i4>>6, k4=(i4&63)*4;
                float4 v=__ldcg((const float4*)(src+bb*256+k4));
                *(float4*)(sH+bb*260+k4)=v;
            }
            __syncthreads();
            const float* hrow=sH+b*260;
            #pragma unroll 4
            for(int k=0;k<256;k+=4){
                ulonglong2 h2=*(const ulonglong2*)(hrow+k);
                #pragma unroll
                for(int r=0;r<8;r++){
                    const ulonglong2* w2=(const ulonglong2*)(wbase+(r>>1)*8192+(r&1)*256+k);
                    FMA2(acc2[r],h2.x,w2->x);
                    FMA2(acc2[r],h2.y,w2->y);
                }
            }
        }
        float acc[8];
        #pragma unroll
        for(int r=0;r<8;r++) acc[r]=unpack_sum(acc2[r])+xr[r];
        float* hw=hxbase+(size_t)((s+1)&1)*GB*256;
        float* hall=g_hall+((size_t)(dir*NL+t)*NB+bg)*NH;
        float hn[2];
        #pragma unroll
        for(int j=0;j<2;j++){
            float cn=sigm_f(acc[2+j])*cst[j]+sigm_f(acc[j])*tanh_f(acc[4+j]);
            cst[j]=cn;
            hn[j]=sigm_f(acc[6+j])*tanh_f(cn);
        }
        *(float2*)(hw+b*256+u0)=make_float2(hn[0],hn[1]);
        *(float2*)(hall+u0)=make_float2(hn[0],hn[1]);
        if(s<NL-1){
            int tn=dir?(NL-2-s):(s+1);
            const float* xgp=g_xg+((size_t)(dir*NL+tn)*NG)*NB;
            #pragma unroll
            for(int r=0;r<8;r++){
                int g=(r>>1)*256 + u0 + (r&1);
                xr[r]=__ldcg(xgp+(size_t)g*NB+bg);
            }
        }
        // syncthreads (cta-scope fence) + tid0 gpu-release composes into the
        // standard two-level flag release; acquire side mirrors it.
        __syncthreads();
        if(tid==0){
            red_release_add(cnt,1u);
            if(s<NL-1){
                unsigned tgt=(unsigned)(GSZ*(s+1));
                while(ld_acquire(cnt)<tgt) __nanosleep(32);
            }
        }
        __syncthreads();
    }
}

// 4) x = hf + hb ; u = squash(primary caps)
__global__ __launch_bounds__(256) void k_combine(){
    int bl=blockIdx.x, b=bl/NL, l=bl%NL, j=threadIdx.x;
    float v=g_hall[((size_t)(0*NL+l)*NB+b)*NH+j]+g_hall[((size_t)(1*NL+l)*NB+b)*NH+j];
    g_x[((size_t)b*NL+l)*NH+j]=v;
    float n2=v*v;
    n2+=__shfl_xor_sync(0xffffffffu,n2,1);
    n2+=__shfl_xor_sync(0xffffffffu,n2,2);
    n2+=__shfl_xor_sync(0xffffffffu,n2,4);
    n2+=__shfl_xor_sync(0xffffffffu,n2,8);
    float f=(n2/(1.f+n2))*rsqrtf(n2+1e-9f);
    g_u[((size_t)b*NCAP+l*16)*16+j]=v*f;
}

// 5) entity gather + attention softmax over L
__global__ __launch_bounds__(256) void k_att(const int* __restrict__ pos1,
                                             const int* __restrict__ pos2){
    __shared__ int se1,se2;
    __shared__ float she[NH];
    __shared__ float sd[NL];
    int b=blockIdx.x, tid=threadIdx.x;
    if(tid<NL){
        if(pos1[b*NL+tid]==68) se1=tid;
        if(pos2[b*NL+tid]==68) se2=tid;
    }
    __syncthreads();
    she[tid]=g_x[((size_t)b*NL+se1)*NH+tid]+g_x[((size_t)b*NL+se2)*NH+tid];
    __syncthreads();
    int warp=tid>>5, lane=tid&31;
    for(int l=warp;l<NL;l+=8){
        const float* xr=g_x+((size_t)b*NL+l)*NH;
        float s=0.f;
        for(int k=lane;k<NH;k+=32) s+=xr[k]*she[k];
        for(int m=16;m;m>>=1) s+=__shfl_xor_sync(0xffffffffu,s,m);
        if(lane==0) sd[l]=s;
    }
    __syncthreads();
    if(tid<32){
        float vals[4],mx=-1e30f;
        #pragma unroll
        for(int q=0;q<4;q++){
            int l=tid+32*q;
            vals[q]=(l<NL)?sd[l]:-1e30f;
            mx=fmaxf(mx,vals[q]);
        }
        for(int m=16;m;m>>=1) mx=fmaxf(mx,__shfl_xor_sync(0xffffffffu,mx,m));
        float es[4],ss=0.f;
        #pragma unroll
        for(int q=0;q<4;q++){
            int l=tid+32*q;
            es[q]=(l<NL)?expf(vals[q]-mx):0.f;
            ss+=es[q];
        }
        for(int m=16;m;m>>=1) ss+=__shfl_xor_sync(0xffffffffu,ss,m);
        float inv=1.f/ss;
        #pragma unroll
        for(int q=0;q<4;q++){
            int l=tid+32*q;
            if(l<NL) g_att[b*NL+l]=es[q]*inv;
        }
    }
}

// 6) softmax(b_route) once
__global__ void k_cbase(const float* __restrict__ br){
    int i=blockIdx.x, lane=threadIdx.x;
    float v=(lane<NCL)?br[i*NCL+lane]:-1e30f;
    float mx=v;
    for(int m=16;m;m>>=1) mx=fmaxf(mx,__shfl_xor_sync(0xffffffffu,mx,m));
    float e=(lane<NCL)?expf(v-mx):0.f;
    float s=e;
    for(int m=16;m;m>>=1) s+=__shfl_xor_sync(0xffffffffu,s,m);
    if(lane<NCL) g_cbase[i*NCL+lane]=e/s;
}

// 7) u_hat[b][i][:] = u[b][i][:16] @ W_caps[i]  -> fp32 output
__global__ __launch_bounds__(256) void k_uhat(const float* __restrict__ Wc){
    __shared__ float Ws[16*NOD];
    __shared__ float Ut[16*132];
    int i=blockIdx.x, tid=threadIdx.x;
    const float* wp=Wc+(size_t)i*16*NOD;
    for(int e=tid;e<16*NOD;e+=256) Ws[e]=wp[e];
    for(int e=tid;e<2048;e+=256){
        int bb_=e>>4,cc=e&15;
        Ut[cc*132+bb_]=g_u[((size_t)bb_*NCAP+i)*16+cc];
    }
    __syncthreads();
    for(int tI=tid;tI<32*76;tI+=256){
        int ot=tI%76, bt=tI/76, o0=ot*4, b0=bt*4;
        float acc[4][4];
        #pragma unroll
        for(int x=0;x<4;x++)
            #pragma unroll
            for(int y=0;y<4;y++) acc[x][y]=0.f;
        #pragma unroll
        for(int cc=0;cc<16;cc++){
            float4 u4=*(const float4*)(Ut+cc*132+b0);
            float4 w4=*(const float4*)(Ws+cc*NOD+o0);
            acc[0][0]+=u4.x*w4.x; acc[0][1]+=u4.x*w4.y; acc[0][2]+=u4.x*w4.z; acc[0][3]+=u4.x*w4.w;
            acc[1][0]+=u4.y*w4.x; acc[1][1]+=u4.y*w4.y; acc[1][2]+=u4.y*w4.z; acc[1][3]+=u4.y*w4.w;
            acc[2][0]+=u4.z*w4.x; acc[2][1]+=u4.z*w4.y; acc[2][2]+=u4.z*w4.z; acc[2][3]+=u4.z*w4.w;
            acc[3][0]+=u4.w*w4.x; acc[3][1]+=u4.w*w4.y; acc[3][2]+=u4.w*w4.z; acc[3][3]+=u4.w*w4.w;
        }
        #pragma unroll
        for(int bi=0;bi<4;bi++){
            float4 r4=make_float4(acc[bi][0],acc[bi][1],acc[bi][2],acc[bi][3]);
            *(float4*)(g_uhat+((size_t)(b0+bi)*NCAP+i)*NOD+o0)=r4;
        }
    }
}

// 8) warp-autonomous fused routing pass: NO block barriers.
__global__ __launch_bounds__(256) void k_route(int mode,const float* __restrict__ b_route){
    int b=blockIdx.x;
    int w=threadIdx.x>>5, lane=threadIdx.x&31;
    int o=lane;
    bool act=(lane<NCL);
    float vd[16];
    if(mode>0){
        #pragma unroll
        for(int q=0;q<4;q++){
            float4 t=act?*(const float4*)(g_v+b*NOD+o*16+q*4):make_float4(0,0,0,0);
            vd[q*4+0]=t.x; vd[q*4+1]=t.y; vd[q*4+2]=t.z; vd[q*4+3]=t.w;
        }
    }
    float sacc[16];
    #pragma unroll
    for(int d=0;d<16;d++) sacc[d]=0.f;
    const int i0=w*(NCAP/NCH);
    float u[16];
    {
        const float* up=g_uhat+((size_t)b*NCAP+i0)*NOD+o*16;
        #pragma unroll
        for(int q=0;q<4;q++){
            float4 t=act?__ldcg((const float4*)(up+q*4)):make_float4(0,0,0,0);
            u[q*4+0]=t.x; u[q*4+1]=t.y; u[q*4+2]=t.z; u[q*4+3]=t.w;
        }
    }
    for(int ii=0;ii<NCAP/NCH;ii++){
        int i=i0+ii;
        float un[16];
        if(ii+1<NCAP/NCH){
            const float* up=g_uhat+((size_t)b*NCAP+i+1)*NOD+o*16;
            #pragma unroll
            for(int q=0;q<4;q++){
                float4 t=act?__ldcg((const float4*)(up+q*4)):make_float4(0,0,0,0);
                un[q*4+0]=t.x; un[q*4+1]=t.y; un[q*4+2]=t.z; un[q*4+3]=t.w;
            }
        }
        float atti=g_att[b*NL+(i>>4)];
        float c;
        if(mode==0){
            c=act?g_cbase[i*NCL+o]*atti:0.f;
        } else {
            float p=0.f;
            #pragma unroll
            for(int d=0;d<16;d++) p+=u[d]*vd[d];
            float nb=0.f;
            if(act){
                float prior=(mode==1)?b_route[i*NCL+o]:g_bb[((size_t)b*NCAP+i)*NCL+o];
                nb=prior+p;
                if(mode==1) g_bb[((size_t)b*NCAP+i)*NCL+o]=nb;
            }
            float e=act?ex2f(1.4426950408889634f*nb):0.f;
            float ss=e;
            ss+=__shfl_xor_sync(0xffffffffu,ss,1);
            ss+=__shfl_xor_sync(0xffffffffu,ss,2);
            ss+=__shfl_xor_sync(0xffffffffu,ss,4);
            ss+=__shfl_xor_sync(0xffffffffu,ss,8);
            ss+=__shfl_xor_sync(0xffffffffu,ss,16);
            c=act?__fdividef(e,ss)*atti:0.f;
        }
        #pragma unroll
        for(int d=0;d<16;d++) sacc[d]+=c*u[d];
        #pragma unroll
        for(int d=0;d<16;d++) u[d]=un[d];
    }
    if(act){
        float* sp=g_spart+((size_t)b*NCH+w)*NOD+o*16;
        #pragma unroll
        for(int q=0;q<4;q++)
            *(float4*)(sp+q*4)=make_float4(sacc[q*4+0],sacc[q*4+1],sacc[q*4+2],sacc[q*4+3]);
    }
}

// 9) reduce partials + squash -> v (or final class lengths)
__global__ __launch_bounds__(320) void k_reduce(int final_out,float* __restrict__ out){
    int b=blockIdx.x, tid=threadIdx.x;
    float s=0.f;
    if(tid<NOD){
        #pragma unroll
        for(int ch=0;ch<NCH;ch++) s+=g_spart[((size_t)b*NCH+ch)*NOD+tid];
    }
    float n2=s*s;
    n2+=__shfl_xor_sync(0xffffffffu,n2,1);
    n2+=__shfl_xor_sync(0xffffffffu,n2,2);
    n2+=__shfl_xor_sync(0xffffffffu,n2,4);
    n2+=__shfl_xor_sync(0xffffffffu,n2,8);
    float f=(n2/(1.f+n2))*rsqrtf(n2+1e-9f);
    if(!final_out){
        if(tid<NOD) g_v[b*NOD+tid]=s*f;
    } else {
        if(tid<NOD&&(tid&15)==0)
            out[b*NCL+(tid>>4)]=sqrtf(n2*f*f+1e-9f);
    }
}

extern "C" void kernel_launch(void* const* d_in,const int* in_sizes,int n_in,
                              void* d_out,int out_size){
    (void)in_sizes;(void)n_in;(void)out_size;
    const int*   word =(const int*)d_in[0];
    const int*   tag  =(const int*)d_in[1];
    const int*   pos1 =(const int*)d_in[2];
    const int*   pos2 =(const int*)d_in[3];
    const float* we   =(const float*)d_in[4];
    const float* te   =(const float*)d_in[5];
    const float* p1e  =(const float*)d_in[6];
    const float* p2e  =(const float*)d_in[7];
    const float* wih_f=(const float*)d_in[8];
    const float* whh_f=(const float*)d_in[9];
    const float* bih_f=(const float*)d_in[10];
    const float* bhh_f=(const float*)d_in[11];
    const float* wih_b=(const float*)d_in[12];
    const float* whh_b=(const float*)d_in[13];
    const float* bih_b=(const float*)d_in[14];
    const float* bhh_b=(const float*)d_in[15];
    const float* Wc   =(const float*)d_in[16];
    const float* br   =(const float*)d_in[17];
    float* out=(float*)d_out;

    cudaFuncSetAttribute(k_lstm, cudaFuncAttributeMaxDynamicSharedMemorySize, LSTM_SMEM);

    k_embed<<<NL*NB,160>>>(word,tag,pos1,pos2,we,te,p1e,p2e);
    k_cbase<<<NCAP,32>>>(br);
    k_xg<<<dim3(32,NL,2),256>>>(wih_f,wih_b,bih_f,bhh_f,bih_b,bhh_b);
    k_zero<<<1,32>>>();
    k_lstm<<<128,256,LSTM_SMEM>>>(whh_f,whh_b);
    k_combine<<<NB*NL,256>>>();
    k_att<<<NB,256>>>(pos1,pos2);
    k_uhat<<<NCAP,256>>>(Wc);
    k_route<<<NB,256>>>(0,br);
    k_reduce<<<NB,320>>>(0,out);
    k_route<<<NB,256>>>(1,br);
    k_reduce<<<NB,320>>>(0,out);
    k_route<<<NB,256>>>(2,br);
    k_reduce<<<NB,320>>>(1,out);
}